// round 11
// baseline (speedup 1.0000x reference)
#include <cuda_runtime.h>
#include <cuda_fp16.h>
#include <cstdint>
#include <cstddef>

#define BATCH 32768
#define HDIM  1024
#define DIN   784

// Scratch buffers (device globals: no allocation allowed)
static __device__ __half  g_z[(size_t)BATCH * HDIM];             // GEMM fp16 out
static __device__ __half  g_h[(size_t)BATCH * HDIM];             // act fp16 out
static __device__ __half  g_xh[(size_t)BATCH * DIN];             // x fp16
static __device__ __half  g_w0h[(size_t)HDIM * DIN];
static __device__ __half  g_w1h[(size_t)HDIM * HDIM];
static __device__ __half  g_w2h[(size_t)HDIM * HDIM];
static __device__ uint8_t g_mb[(size_t)BATCH * HDIM];            // packed mask

// ---------------------------------------------------------------------------
// helpers
// ---------------------------------------------------------------------------
__device__ __forceinline__ uint32_t smem_u32(const void* p) {
    return (uint32_t)__cvta_generic_to_shared(p);
}
#define SWZ128(o) ((o) ^ (((o) >> 3) & 0x70))

__device__ __forceinline__ void cp16(uint32_t dst, const void* src, int bytes) {
    asm volatile("cp.async.cg.shared.global [%0], [%1], 16, %2;\n"
                 :: "r"(dst), "l"(src), "r"(bytes));
}
__device__ __forceinline__ void cp_commit() {
    asm volatile("cp.async.commit_group;\n");
}

__device__ __forceinline__ void ldm_x4(uint32_t (&r)[4], uint32_t addr) {
    asm volatile("ldmatrix.sync.aligned.m8n8.x4.shared.b16 {%0,%1,%2,%3}, [%4];"
                 : "=r"(r[0]), "=r"(r[1]), "=r"(r[2]), "=r"(r[3]) : "r"(addr));
}

__device__ __forceinline__ void mma_fp16(float d[4], const uint32_t a[4],
                                         const uint32_t b0, const uint32_t b1) {
    asm volatile(
        "mma.sync.aligned.m16n8k16.row.col.f32.f16.f16.f32 "
        "{%0,%1,%2,%3}, {%4,%5,%6,%7}, {%8,%9}, {%0,%1,%2,%3};\n"
        : "+f"(d[0]), "+f"(d[1]), "+f"(d[2]), "+f"(d[3])
        : "r"(a[0]), "r"(a[1]), "r"(a[2]), "r"(a[3]), "r"(b0), "r"(b1));
}

// ---------------------------------------------------------------------------
// fp32 -> fp16 convert (grid-stride, float4 granularity)
// ---------------------------------------------------------------------------
__global__ __launch_bounds__(256)
void f2h_kernel(const float* __restrict__ src, __half* __restrict__ dst, int n4) {
    for (int i = blockIdx.x * 256 + threadIdx.x; i < n4; i += gridDim.x * 256) {
        float4 v = *(const float4*)(src + (size_t)i * 4);
        __half2 h0 = __floats2half2_rn(v.x, v.y);
        __half2 h1 = __floats2half2_rn(v.z, v.w);
        uint2 u;
        u.x = *(uint32_t*)&h0;
        u.y = *(uint32_t*)&h1;
        *(uint2*)(dst + (size_t)i * 4) = u;
    }
}

// ---------------------------------------------------------------------------
// GEMM: C[M, HDIM](fp16) = A[M,K](f16) @ W[HDIM,K](f16)^T + bias
// CTA 128x128, BK=64 halves, 3-stage cp.async, SW128, ldmatrix, m16n8k16,
// f32 accum. 8 warps, warp tile 64x32. Single barrier per k-iter + kk-level
// fragment double buffering.  (R8 config — best measured.)
// Fused: copies a 16384-element slice of the next layer's dropout mask to the
// output region (f32) and to a packed uint8 buffer; this DRAM traffic hides
// under the tensor-bound mainloop.
// ---------------------------------------------------------------------------
#define GSTAGES 3
#define AB_BYTES 16384            // 128 rows * 128B
#define STG_BYTES (2 * AB_BYTES)

__device__ __forceinline__ void load_chunk(const __half* __restrict__ A,
                                           const __half* __restrict__ W,
                                           int K, size_t blockRow, int blockCol,
                                           int k0, uint32_t stage_base, int tid) {
#pragma unroll
    for (int i = 0; i < 4; i++) {
        int u = tid + i * 256;          // 0..1023
        int row = u >> 3;               // 0..127
        int c16 = u & 7;
        int col = k0 + c16 * 8;
        int vb = (col + 8 <= K) ? 16 : 0;
        const __half* src = A + (blockRow + (size_t)row) * (size_t)K +
                            (vb ? col : k0);
        uint32_t off = (uint32_t)(row * 128 + c16 * 16);
        cp16(stage_base + SWZ128(off), src, vb);
    }
#pragma unroll
    for (int i = 0; i < 4; i++) {
        int u = tid + i * 256;
        int row = u >> 3;
        int c16 = u & 7;
        int col = k0 + c16 * 8;
        int vb = (col + 8 <= K) ? 16 : 0;
        const __half* src = W + (size_t)(blockCol + row) * (size_t)K +
                            (vb ? col : k0);
        uint32_t off = (uint32_t)(row * 128 + c16 * 16);
        cp16(stage_base + AB_BYTES + SWZ128(off), src, vb);
    }
}

__global__ __launch_bounds__(256)
void gemm_fp16_kernel(const __half* __restrict__ A, const __half* __restrict__ W,
                      const float* __restrict__ bias, __half* __restrict__ C,
                      int K,
                      const float* __restrict__ mask_src,
                      float* __restrict__ mask_f32_dst,
                      uint8_t* __restrict__ mask_u8_dst) {
    extern __shared__ char dsm[];
    const uint32_t sbase = (smem_u32(dsm) + 1023u) & ~1023u;

    const int tid  = threadIdx.x;
    const int lane = tid & 31;
    const int warp = tid >> 5;
    const int wm   = (warp & 1) * 64;
    const int wn   = (warp >> 1) * 32;

    const size_t blockRow = (size_t)blockIdx.y * 128;
    const int    blockCol = blockIdx.x * 128;

    float acc[4][4][4];
#pragma unroll
    for (int mt = 0; mt < 4; mt++)
#pragma unroll
        for (int nt = 0; nt < 4; nt++)
#pragma unroll
            for (int r = 0; r < 4; r++) acc[mt][nt][r] = 0.f;

    const int nK = (K + 63) / 64;

    // ldmatrix lane-addressing precompute
    const int lrow = lane & 7;
    const int lmat = lane >> 3;
    const int a_radd = (lmat & 1) * 8;
    const int a_kadd = (lmat >> 1) * 16;
    const int b_nadd = (lmat >> 1) * 8;
    const int b_kadd = (lmat & 1) * 16;

    // Prologue: stages 0, 1
#pragma unroll
    for (int s = 0; s < GSTAGES - 1; s++) {
        load_chunk(A, W, K, blockRow, blockCol, s * 64,
                   sbase + (uint32_t)s * STG_BYTES, tid);
        cp_commit();
    }
    asm volatile("cp.async.wait_group 1;\n");
    __syncthreads();

    uint32_t af[2][4][4];
    uint32_t bf[2][2][4];

#define LOAD_FRAGS(buf, stageA, stageB, kbyte)                                \
    do {                                                                      \
        _Pragma("unroll")                                                     \
        for (int mt = 0; mt < 4; mt++) {                                      \
            int row = wm + mt * 16 + a_radd + lrow;                           \
            uint32_t off = (uint32_t)(row * 128 + (kbyte) + a_kadd);          \
            ldm_x4(af[buf][mt], (stageA) + SWZ128(off));                      \
        }                                                                     \
        _Pragma("unroll")                                                     \
        for (int np = 0; np < 2; np++) {                                      \
            int row = wn + np * 16 + b_nadd + lrow;                           \
            uint32_t off = (uint32_t)(row * 128 + (kbyte) + b_kadd);          \
            ldm_x4(bf[buf][np], (stageB) + SWZ128(off));                      \
        }                                                                     \
    } while (0)

    {
        uint32_t aB0 = sbase;
        uint32_t bB0 = sbase + AB_BYTES;
        LOAD_FRAGS(0, aB0, bB0, 0);
    }

    // Fused mask-copy setup: 2048 CTAs x 16384 elems = BATCH*HDIM
    const size_t mcbase =
        ((size_t)blockIdx.y * gridDim.x + blockIdx.x) * 16384 + (size_t)tid * 4;

    for (int kt = 0; kt < nK; ++kt) {
        const uint32_t aB = sbase + (uint32_t)(kt % GSTAGES) * STG_BYTES;
        const uint32_t bB = aB + AB_BYTES;

#pragma unroll
        for (int kk = 0; kk < 4; kk++) {
            const int cur = kk & 1;
            if (kk < 3) LOAD_FRAGS(cur ^ 1, aB, bB, (kk + 1) * 32);
#pragma unroll
            for (int mt = 0; mt < 4; mt++) {
#pragma unroll
                for (int nt = 0; nt < 4; nt++) {
                    mma_fp16(acc[mt][nt], af[cur][mt],
                             bf[cur][nt >> 1][(nt & 1) * 2],
                             bf[cur][nt >> 1][(nt & 1) * 2 + 1]);
                }
            }
        }

        // interleave one float4 of mask copy per k-iter (16 iters max used)
        if (kt < 16) {
            size_t idx = mcbase + (size_t)kt * 1024;
            float4 mv = *(const float4*)(mask_src + idx);
            *(float4*)(mask_f32_dst + idx) = mv;
            uchar4 pb;
            pb.x = mv.x != 0.0f;
            pb.y = mv.y != 0.0f;
            pb.z = mv.z != 0.0f;
            pb.w = mv.w != 0.0f;
            *(uchar4*)(mask_u8_dst + idx) = pb;
        }

        int pf = kt + GSTAGES - 1;
        if (pf < nK)
            load_chunk(A, W, K, blockRow, blockCol, pf * 64,
                       sbase + (uint32_t)(pf % GSTAGES) * STG_BYTES, tid);
        cp_commit();
        asm volatile("cp.async.wait_group 1;\n");
        __syncthreads();

        if (kt + 1 < nK) {
            uint32_t aN = sbase + (uint32_t)((kt + 1) % GSTAGES) * STG_BYTES;
            uint32_t bN = aN + AB_BYTES;
            LOAD_FRAGS(0, aN, bN, 0);
        }
    }

    // Tail of mask copy when nK < 16 (K=784 -> nK=13: finish iters 13..15)
    for (int it = nK; it < 16; ++it) {
        size_t idx = mcbase + (size_t)it * 1024;
        float4 mv = *(const float4*)(mask_src + idx);
        *(float4*)(mask_f32_dst + idx) = mv;
        uchar4 pb;
        pb.x = mv.x != 0.0f;
        pb.y = mv.y != 0.0f;
        pb.z = mv.z != 0.0f;
        pb.w = mv.w != 0.0f;
        *(uchar4*)(mask_u8_dst + idx) = pb;
    }

    // Epilogue: bias + fp16 store
    const int g  = lane >> 2;
    const int tq = lane & 3;
#pragma unroll
    for (int mt = 0; mt < 4; mt++) {
        size_t row = blockRow + (size_t)(wm + mt * 16 + g);
#pragma unroll
        for (int nt = 0; nt < 4; nt++) {
            int c0 = blockCol + wn + nt * 8 + tq * 2;
            float bv0 = __ldg(bias + c0), bv1 = __ldg(bias + c0 + 1);
            __half2 v0 = __floats2half2_rn(acc[mt][nt][0] + bv0,
                                           acc[mt][nt][1] + bv1);
            __half2 v1 = __floats2half2_rn(acc[mt][nt][2] + bv0,
                                           acc[mt][nt][3] + bv1);
            *(__half2*)(C + row * HDIM + c0)       = v0;
            *(__half2*)(C + (row + 8) * HDIM + c0) = v1;
        }
    }
}

// ---------------------------------------------------------------------------
// activation helpers
// ---------------------------------------------------------------------------
__device__ __forceinline__ float tanh_ap(float x) {
    float r;
    asm("tanh.approx.f32 %0, %1;" : "=f"(r) : "f"(x));
    return r;
}

__device__ __forceinline__ float act_eval(float x, int c, float M3, float inv3,
                                          float M4, float inv4) {
    float av;
    if (c == 0)      av = fmaxf(x, 0.0f);
    else if (c == 1) av = tanh_ap(x);
    else if (c == 2) av = 0.5f * tanh_ap(0.5f * x) + 0.5f;
    else if (c == 3) av = __expf(x - M3) * inv3;
    else if (c == 4) av = __expf(-x - M4) * inv4;
    else if (c == 5) av = 0.5f * x * (1.0f + erff(x * 0.70710678118654752f));
    else             av = (x >= 0.0f) ? x : 0.01f * x;
    return av;
}

// ---------------------------------------------------------------------------
// Warp-per-row activation: reads fp16 GEMM out + byte mask, writes fp16
// (act*mask*2). Mask passthrough already done by the producer GEMM.
// ---------------------------------------------------------------------------
__global__ __launch_bounds__(128)
void act_kernel(const __half* __restrict__ zbuf, const int* __restrict__ tids,
                const uint8_t* __restrict__ maskb, __half* __restrict__ hout) {
    const int lane = threadIdx.x & 31;
    const size_t row = (size_t)blockIdx.x * 4 + (threadIdx.x >> 5);
    const size_t base = row * HDIM + lane * 4;

    float z[8][4];
    uchar4 mb[8];
    int4 t4[8];
#pragma unroll
    for (int i = 0; i < 8; i++) {
        uint2 u = *(const uint2*)(zbuf + base + i * 128);
        __half2 h0 = *(__half2*)&u.x;
        __half2 h1 = *(__half2*)&u.y;
        float2 f0 = __half22float2(h0);
        float2 f1 = __half22float2(h1);
        z[i][0] = f0.x; z[i][1] = f0.y; z[i][2] = f1.x; z[i][3] = f1.y;
        mb[i] = *(const uchar4*)(maskb + base + i * 128);
        t4[i] = *(const int4*)(tids + lane * 4 + i * 128);
    }

    float a = -1e30f, b = -1e30f;
#pragma unroll
    for (int i = 0; i < 8; i++) {
        int ty[4] = {t4[i].x, t4[i].y, t4[i].z, t4[i].w};
#pragma unroll
        for (int s = 0; s < 4; s++) {
            if (ty[s] == 3) a = fmaxf(a, z[i][s]);
            if (ty[s] == 4) b = fmaxf(b, -z[i][s]);
        }
    }
#pragma unroll
    for (int o = 16; o; o >>= 1) {
        a = fmaxf(a, __shfl_xor_sync(0xffffffffu, a, o));
        b = fmaxf(b, __shfl_xor_sync(0xffffffffu, b, o));
    }
    float sa = 0.f, sb = 0.f;
#pragma unroll
    for (int i = 0; i < 8; i++) {
        int ty[4] = {t4[i].x, t4[i].y, t4[i].z, t4[i].w};
#pragma unroll
        for (int s = 0; s < 4; s++) {
            if (ty[s] == 3) sa += __expf(z[i][s] - a);
            if (ty[s] == 4) sb += __expf(-z[i][s] - b);
        }
    }
#pragma unroll
    for (int o = 16; o; o >>= 1) {
        sa += __shfl_xor_sync(0xffffffffu, sa, o);
        sb += __shfl_xor_sync(0xffffffffu, sb, o);
    }
    float inv3 = __frcp_rn(sa), inv4 = __frcp_rn(sb);

#pragma unroll
    for (int i = 0; i < 8; i++) {
        int ty[4] = {t4[i].x, t4[i].y, t4[i].z, t4[i].w};
        float mk[4] = {(float)mb[i].x, (float)mb[i].y,
                       (float)mb[i].z, (float)mb[i].w};
        float r0 = act_eval(z[i][0], ty[0], a, inv3, b, inv4) * mk[0] * 2.0f;
        float r1 = act_eval(z[i][1], ty[1], a, inv3, b, inv4) * mk[1] * 2.0f;
        float r2 = act_eval(z[i][2], ty[2], a, inv3, b, inv4) * mk[2] * 2.0f;
        float r3 = act_eval(z[i][3], ty[3], a, inv3, b, inv4) * mk[3] * 2.0f;
        __half2 h0 = __floats2half2_rn(r0, r1);
        __half2 h1 = __floats2half2_rn(r2, r3);
        uint2 u;
        u.x = *(uint32_t*)&h0;
        u.y = *(uint32_t*)&h1;
        *(uint2*)(hout + base + i * 128) = u;
    }
}

// ---------------------------------------------------------------------------
// act3 + head fused: activation, mask3*2 (byte mask), dot with W3 (10x1024),
// log_softmax.
// ---------------------------------------------------------------------------
__global__ __launch_bounds__(128)
void act3_head_kernel(const __half* __restrict__ zbuf, const int* __restrict__ tids,
                      const uint8_t* __restrict__ maskb,
                      const float* __restrict__ W3, const float* __restrict__ b3,
                      float* __restrict__ out) {
    const int lane = threadIdx.x & 31;
    const size_t row = (size_t)blockIdx.x * 4 + (threadIdx.x >> 5);
    const size_t base = row * HDIM + lane * 4;

    float z[8][4];
    uchar4 mb[8];
    int4 t4[8];
#pragma unroll
    for (int i = 0; i < 8; i++) {
        uint2 u = *(const uint2*)(zbuf + base + i * 128);
        __half2 h0 = *(__half2*)&u.x;
        __half2 h1 = *(__half2*)&u.y;
        float2 f0 = __half22float2(h0);
        float2 f1 = __half22float2(h1);
        z[i][0] = f0.x; z[i][1] = f0.y; z[i][2] = f1.x; z[i][3] = f1.y;
        mb[i] = *(const uchar4*)(maskb + base + i * 128);
        t4[i] = *(const int4*)(tids + lane * 4 + i * 128);
    }

    float a = -1e30f, b = -1e30f;
#pragma unroll
    for (int i = 0; i < 8; i++) {
        int ty[4] = {t4[i].x, t4[i].y, t4[i].z, t4[i].w};
#pragma unroll
        for (int s = 0; s < 4; s++) {
            if (ty[s] == 3) a = fmaxf(a, z[i][s]);
            if (ty[s] == 4) b = fmaxf(b, -z[i][s]);
        }
    }
#pragma unroll
    for (int o = 16; o; o >>= 1) {
        a = fmaxf(a, __shfl_xor_sync(0xffffffffu, a, o));
        b = fmaxf(b, __shfl_xor_sync(0xffffffffu, b, o));
    }
    float sa = 0.f, sb = 0.f;
#pragma unroll
    for (int i = 0; i < 8; i++) {
        int ty[4] = {t4[i].x, t4[i].y, t4[i].z, t4[i].w};
#pragma unroll
        for (int s = 0; s < 4; s++) {
            if (ty[s] == 3) sa += __expf(z[i][s] - a);
            if (ty[s] == 4) sb += __expf(-z[i][s] - b);
        }
    }
#pragma unroll
    for (int o = 16; o; o >>= 1) {
        sa += __shfl_xor_sync(0xffffffffu, sa, o);
        sb += __shfl_xor_sync(0xffffffffu, sb, o);
    }
    float inv3 = __frcp_rn(sa), inv4 = __frcp_rn(sb);

    float acc[10];
#pragma unroll
    for (int j = 0; j < 10; j++) acc[j] = 0.f;

#pragma unroll
    for (int i = 0; i < 8; i++) {
        int ty[4] = {t4[i].x, t4[i].y, t4[i].z, t4[i].w};
        float mk[4] = {(float)mb[i].x, (float)mb[i].y,
                       (float)mb[i].z, (float)mb[i].w};
        float r0 = act_eval(z[i][0], ty[0], a, inv3, b, inv4) * mk[0] * 2.0f;
        float r1 = act_eval(z[i][1], ty[1], a, inv3, b, inv4) * mk[1] * 2.0f;
        float r2 = act_eval(z[i][2], ty[2], a, inv3, b, inv4) * mk[2] * 2.0f;
        float r3 = act_eval(z[i][3], ty[3], a, inv3, b, inv4) * mk[3] * 2.0f;
        int colbase = lane * 4 + i * 128;
#pragma unroll
        for (int j = 0; j < 10; j++) {
            float4 w = *(const float4*)(W3 + (size_t)j * HDIM + colbase);
            acc[j] += r0 * w.x + r1 * w.y + r2 * w.z + r3 * w.w;
        }
    }
#pragma unroll
    for (int j = 0; j < 10; j++)
#pragma unroll
        for (int o = 16; o; o >>= 1)
            acc[j] += __shfl_xor_sync(0xffffffffu, acc[j], o);

    float logits[10];
    float m = -1e30f;
#pragma unroll
    for (int j = 0; j < 10; j++) {
        logits[j] = acc[j] + __ldg(b3 + j);
        m = fmaxf(m, logits[j]);
    }
    float s = 0.f;
#pragma unroll
    for (int j = 0; j < 10; j++) s += __expf(logits[j] - m);
    float lse = m + logf(s);
    if (lane == 0) {
#pragma unroll
        for (int j = 0; j < 10; j++) out[row * 10 + j] = logits[j] - lse;
    }
}

// ---------------------------------------------------------------------------
// Launch
// ---------------------------------------------------------------------------
extern "C" void kernel_launch(void* const* d_in, const int* in_sizes, int n_in,
                              void* d_out, int out_size) {
    const float* x     = (const float*)d_in[0];
    const float* W0    = (const float*)d_in[1];
    const float* b0    = (const float*)d_in[2];
    const float* W1    = (const float*)d_in[3];
    const float* b1    = (const float*)d_in[4];
    const float* W2    = (const float*)d_in[5];
    const float* b2    = (const float*)d_in[6];
    const float* W3    = (const float*)d_in[7];
    const float* b3    = (const float*)d_in[8];
    const float* mask1 = (const float*)d_in[9];
    const float* mask2 = (const float*)d_in[10];
    const float* mask3 = (const float*)d_in[11];
    const int* type_ids = (const int*)d_in[12];

    __half* zbuf = nullptr;
    __half* hbuf = nullptr;
    __half* xh   = nullptr;
    __half* w0h  = nullptr;
    __half* w1h  = nullptr;
    __half* w2h  = nullptr;
    uint8_t* mb  = nullptr;
    cudaGetSymbolAddress((void**)&zbuf, g_z);
    cudaGetSymbolAddress((void**)&hbuf, g_h);
    cudaGetSymbolAddress((void**)&xh, g_xh);
    cudaGetSymbolAddress((void**)&w0h, g_w0h);
    cudaGetSymbolAddress((void**)&w1h, g_w1h);
    cudaGetSymbolAddress((void**)&w2h, g_w2h);
    cudaGetSymbolAddress((void**)&mb, g_mb);
    float* out = (float*)d_out;

    const int smemBytes = GSTAGES * STG_BYTES + 1024;
    cudaFuncSetAttribute(gemm_fp16_kernel,
                         cudaFuncAttributeMaxDynamicSharedMemorySize, smemBytes);

    // fp32 -> fp16 conversions
    f2h_kernel<<<1024, 256>>>(x, xh, (int)((size_t)BATCH * DIN / 4));
    f2h_kernel<<<256, 256>>>(W0, w0h, HDIM * DIN / 4);
    f2h_kernel<<<256, 256>>>(W1, w1h, HDIM * HDIM / 4);
    f2h_kernel<<<256, 256>>>(W2, w2h, HDIM * HDIM / 4);

    const size_t maskElems = (size_t)BATCH * HDIM;
    float* mdst = out + (size_t)BATCH * 10;

    dim3 gg(HDIM / 128, BATCH / 128);
    gemm_fp16_kernel<<<gg, 256, smemBytes>>>(xh, w0h, b0, zbuf, DIN,
                                             mask1, mdst, mb);
    act_kernel<<<BATCH / 4, 128>>>(zbuf, type_ids, mb, hbuf);
    gemm_fp16_kernel<<<gg, 256, smemBytes>>>(hbuf, w1h, b1, zbuf, HDIM,
                                             mask2, mdst + maskElems, mb);
    act_kernel<<<BATCH / 4, 128>>>(zbuf, type_ids + HDIM, mb, hbuf);
    gemm_fp16_kernel<<<gg, 256, smemBytes>>>(hbuf, w2h, b2, zbuf, HDIM,
                                             mask3, mdst + 2 * maskElems, mb);
    act3_head_kernel<<<BATCH / 4, 128>>>(zbuf, type_ids + 2 * HDIM, mb,
                                         W3, b3, out);
}

// round 12
// speedup vs baseline: 1.0459x; 1.0459x over previous
#include <cuda_runtime.h>
#include <cuda_fp16.h>
#include <cstdint>
#include <cstddef>

#define BATCH 32768
#define HDIM  1024
#define DIN   784

// Scratch buffers (device globals: no allocation allowed)
static __device__ __half  g_z[(size_t)BATCH * HDIM];             // GEMM fp16 out
static __device__ __half  g_h[(size_t)BATCH * HDIM];             // act fp16 out
static __device__ __half  g_xh[(size_t)BATCH * DIN];             // x fp16
static __device__ __half  g_w0h[(size_t)HDIM * DIN];
static __device__ __half  g_w1h[(size_t)HDIM * HDIM];
static __device__ __half  g_w2h[(size_t)HDIM * HDIM];
static __device__ uint8_t g_mb[(size_t)BATCH * HDIM];            // packed mask

// ---------------------------------------------------------------------------
// helpers
// ---------------------------------------------------------------------------
__device__ __forceinline__ uint32_t smem_u32(const void* p) {
    return (uint32_t)__cvta_generic_to_shared(p);
}
#define SWZ128(o) ((o) ^ (((o) >> 3) & 0x70))

__device__ __forceinline__ void cp16(uint32_t dst, const void* src, int bytes) {
    asm volatile("cp.async.cg.shared.global [%0], [%1], 16, %2;\n"
                 :: "r"(dst), "l"(src), "r"(bytes));
}
__device__ __forceinline__ void cp_commit() {
    asm volatile("cp.async.commit_group;\n");
}

__device__ __forceinline__ void ldm_x4(uint32_t (&r)[4], uint32_t addr) {
    asm volatile("ldmatrix.sync.aligned.m8n8.x4.shared.b16 {%0,%1,%2,%3}, [%4];"
                 : "=r"(r[0]), "=r"(r[1]), "=r"(r[2]), "=r"(r[3]) : "r"(addr));
}

__device__ __forceinline__ void mma_fp16(float d[4], const uint32_t a[4],
                                         const uint32_t b0, const uint32_t b1) {
    asm volatile(
        "mma.sync.aligned.m16n8k16.row.col.f32.f16.f16.f32 "
        "{%0,%1,%2,%3}, {%4,%5,%6,%7}, {%8,%9}, {%0,%1,%2,%3};\n"
        : "+f"(d[0]), "+f"(d[1]), "+f"(d[2]), "+f"(d[3])
        : "r"(a[0]), "r"(a[1]), "r"(a[2]), "r"(a[3]), "r"(b0), "r"(b1));
}

// ---------------------------------------------------------------------------
// fp32 -> fp16 convert (grid-stride, float4 granularity)
// ---------------------------------------------------------------------------
__global__ __launch_bounds__(256)
void f2h_kernel(const float* __restrict__ src, __half* __restrict__ dst, int n4) {
    for (int i = blockIdx.x * 256 + threadIdx.x; i < n4; i += gridDim.x * 256) {
        float4 v = *(const float4*)(src + (size_t)i * 4);
        __half2 h0 = __floats2half2_rn(v.x, v.y);
        __half2 h1 = __floats2half2_rn(v.z, v.w);
        uint2 u;
        u.x = *(uint32_t*)&h0;
        u.y = *(uint32_t*)&h1;
        *(uint2*)(dst + (size_t)i * 4) = u;
    }
}

// ---------------------------------------------------------------------------
// GEMM: C[M, HDIM](fp16) = A[M,K](f16) @ W[HDIM,K](f16)^T + bias
// CTA 128x128, BK=64 halves, 3-stage cp.async, SW128, ldmatrix, m16n8k16,
// f32 accum. 8 warps, warp tile 64x32. Single barrier per k-iter + kk-level
// fragment double buffering.  (R8 mainloop — best measured; untouched.)
// Block specialization: blocks >= NGEMMB are pure copy CTAs that stream the
// next layer's dropout mask to the output region (f32) and a packed u8
// buffer, overlapping the tensor-bound GEMM waves.
// ---------------------------------------------------------------------------
#define GSTAGES 3
#define AB_BYTES 16384            // 128 rows * 128B
#define STG_BYTES (2 * AB_BYTES)
#define NGEMMB (256 * 8)          // 2048 GEMM CTAs (M/128 x HDIM/128)
#define COPYB  256                // copy CTAs appended at the end

__device__ __forceinline__ void load_chunk(const __half* __restrict__ A,
                                           const __half* __restrict__ W,
                                           int K, size_t blockRow, int blockCol,
                                           int k0, uint32_t stage_base, int tid) {
#pragma unroll
    for (int i = 0; i < 4; i++) {
        int u = tid + i * 256;          // 0..1023
        int row = u >> 3;               // 0..127
        int c16 = u & 7;
        int col = k0 + c16 * 8;
        int vb = (col + 8 <= K) ? 16 : 0;
        const __half* src = A + (blockRow + (size_t)row) * (size_t)K +
                            (vb ? col : k0);
        uint32_t off = (uint32_t)(row * 128 + c16 * 16);
        cp16(stage_base + SWZ128(off), src, vb);
    }
#pragma unroll
    for (int i = 0; i < 4; i++) {
        int u = tid + i * 256;
        int row = u >> 3;
        int c16 = u & 7;
        int col = k0 + c16 * 8;
        int vb = (col + 8 <= K) ? 16 : 0;
        const __half* src = W + (size_t)(blockCol + row) * (size_t)K +
                            (vb ? col : k0);
        uint32_t off = (uint32_t)(row * 128 + c16 * 16);
        cp16(stage_base + AB_BYTES + SWZ128(off), src, vb);
    }
}

__global__ __launch_bounds__(256)
void gemm_fp16_kernel(const __half* __restrict__ A, const __half* __restrict__ W,
                      const float* __restrict__ bias, __half* __restrict__ C,
                      int K,
                      const float* __restrict__ mask_src,
                      float* __restrict__ mask_f32_dst,
                      uint8_t* __restrict__ mask_u8_dst) {
    const int tid = threadIdx.x;

    // ---- copy CTAs: stream mask passthrough + u8 pack, then exit ----
    if (blockIdx.x >= NGEMMB) {
        const int cb = blockIdx.x - NGEMMB;
        const int total4 = BATCH * HDIM / 4;          // 8M float4
        for (int i = cb * 256 + tid; i < total4; i += COPYB * 256) {
            float4 mv = *(const float4*)(mask_src + (size_t)i * 4);
            *(float4*)(mask_f32_dst + (size_t)i * 4) = mv;
            uchar4 pb;
            pb.x = mv.x != 0.0f;
            pb.y = mv.y != 0.0f;
            pb.z = mv.z != 0.0f;
            pb.w = mv.w != 0.0f;
            *(uchar4*)(mask_u8_dst + (size_t)i * 4) = pb;
        }
        return;
    }

    extern __shared__ char dsm[];
    const uint32_t sbase = (smem_u32(dsm) + 1023u) & ~1023u;

    const int lane = tid & 31;
    const int warp = tid >> 5;
    const int wm   = (warp & 1) * 64;
    const int wn   = (warp >> 1) * 32;

    const int    bx = blockIdx.x & 7;          // 0..7 (N tiles)
    const int    by = blockIdx.x >> 3;         // 0..255 (M tiles)
    const size_t blockRow = (size_t)by * 128;
    const int    blockCol = bx * 128;

    float acc[4][4][4];
#pragma unroll
    for (int mt = 0; mt < 4; mt++)
#pragma unroll
        for (int nt = 0; nt < 4; nt++)
#pragma unroll
            for (int r = 0; r < 4; r++) acc[mt][nt][r] = 0.f;

    const int nK = (K + 63) / 64;

    // ldmatrix lane-addressing precompute
    const int lrow = lane & 7;
    const int lmat = lane >> 3;
    const int a_radd = (lmat & 1) * 8;
    const int a_kadd = (lmat >> 1) * 16;
    const int b_nadd = (lmat >> 1) * 8;
    const int b_kadd = (lmat & 1) * 16;

    // Prologue: stages 0, 1
#pragma unroll
    for (int s = 0; s < GSTAGES - 1; s++) {
        load_chunk(A, W, K, blockRow, blockCol, s * 64,
                   sbase + (uint32_t)s * STG_BYTES, tid);
        cp_commit();
    }
    asm volatile("cp.async.wait_group 1;\n");
    __syncthreads();

    uint32_t af[2][4][4];
    uint32_t bf[2][2][4];

#define LOAD_FRAGS(buf, stageA, stageB, kbyte)                                \
    do {                                                                      \
        _Pragma("unroll")                                                     \
        for (int mt = 0; mt < 4; mt++) {                                      \
            int row = wm + mt * 16 + a_radd + lrow;                           \
            uint32_t off = (uint32_t)(row * 128 + (kbyte) + a_kadd);          \
            ldm_x4(af[buf][mt], (stageA) + SWZ128(off));                      \
        }                                                                     \
        _Pragma("unroll")                                                     \
        for (int np = 0; np < 2; np++) {                                      \
            int row = wn + np * 16 + b_nadd + lrow;                           \
            uint32_t off = (uint32_t)(row * 128 + (kbyte) + b_kadd);          \
            ldm_x4(bf[buf][np], (stageB) + SWZ128(off));                      \
        }                                                                     \
    } while (0)

    {
        uint32_t aB0 = sbase;
        uint32_t bB0 = sbase + AB_BYTES;
        LOAD_FRAGS(0, aB0, bB0, 0);
    }

    for (int kt = 0; kt < nK; ++kt) {
        const uint32_t aB = sbase + (uint32_t)(kt % GSTAGES) * STG_BYTES;
        const uint32_t bB = aB + AB_BYTES;

#pragma unroll
        for (int kk = 0; kk < 4; kk++) {
            const int cur = kk & 1;
            if (kk < 3) LOAD_FRAGS(cur ^ 1, aB, bB, (kk + 1) * 32);
#pragma unroll
            for (int mt = 0; mt < 4; mt++) {
#pragma unroll
                for (int nt = 0; nt < 4; nt++) {
                    mma_fp16(acc[mt][nt], af[cur][mt],
                             bf[cur][nt >> 1][(nt & 1) * 2],
                             bf[cur][nt >> 1][(nt & 1) * 2 + 1]);
                }
            }
        }

        int pf = kt + GSTAGES - 1;
        if (pf < nK)
            load_chunk(A, W, K, blockRow, blockCol, pf * 64,
                       sbase + (uint32_t)(pf % GSTAGES) * STG_BYTES, tid);
        cp_commit();
        asm volatile("cp.async.wait_group 1;\n");
        __syncthreads();

        if (kt + 1 < nK) {
            uint32_t aN = sbase + (uint32_t)((kt + 1) % GSTAGES) * STG_BYTES;
            uint32_t bN = aN + AB_BYTES;
            LOAD_FRAGS(0, aN, bN, 0);
        }
    }

    // Epilogue: bias + fp16 store
    const int g  = lane >> 2;
    const int tq = lane & 3;
#pragma unroll
    for (int mt = 0; mt < 4; mt++) {
        size_t row = blockRow + (size_t)(wm + mt * 16 + g);
#pragma unroll
        for (int nt = 0; nt < 4; nt++) {
            int c0 = blockCol + wn + nt * 8 + tq * 2;
            float bv0 = __ldg(bias + c0), bv1 = __ldg(bias + c0 + 1);
            __half2 v0 = __floats2half2_rn(acc[mt][nt][0] + bv0,
                                           acc[mt][nt][1] + bv1);
            __half2 v1 = __floats2half2_rn(acc[mt][nt][2] + bv0,
                                           acc[mt][nt][3] + bv1);
            *(__half2*)(C + row * HDIM + c0)       = v0;
            *(__half2*)(C + (row + 8) * HDIM + c0) = v1;
        }
    }
}

// ---------------------------------------------------------------------------
// activation helpers
// ---------------------------------------------------------------------------
__device__ __forceinline__ float tanh_ap(float x) {
    float r;
    asm("tanh.approx.f32 %0, %1;" : "=f"(r) : "f"(x));
    return r;
}

__device__ __forceinline__ float act_eval(float x, int c, float M3, float inv3,
                                          float M4, float inv4) {
    float av;
    if (c == 0)      av = fmaxf(x, 0.0f);
    else if (c == 1) av = tanh_ap(x);
    else if (c == 2) av = 0.5f * tanh_ap(0.5f * x) + 0.5f;
    else if (c == 3) av = __expf(x - M3) * inv3;
    else if (c == 4) av = __expf(-x - M4) * inv4;
    else if (c == 5) av = 0.5f * x * (1.0f + erff(x * 0.70710678118654752f));
    else             av = (x >= 0.0f) ? x : 0.01f * x;
    return av;
}

// ---------------------------------------------------------------------------
// Warp-per-row activation: reads fp16 GEMM out + byte mask, writes fp16
// (act*mask*2). Mask passthrough already done by the producer GEMM.
// ---------------------------------------------------------------------------
__global__ __launch_bounds__(128)
void act_kernel(const __half* __restrict__ zbuf, const int* __restrict__ tids,
                const uint8_t* __restrict__ maskb, __half* __restrict__ hout) {
    const int lane = threadIdx.x & 31;
    const size_t row = (size_t)blockIdx.x * 4 + (threadIdx.x >> 5);
    const size_t base = row * HDIM + lane * 4;

    float z[8][4];
    uchar4 mb[8];
    int4 t4[8];
#pragma unroll
    for (int i = 0; i < 8; i++) {
        uint2 u = *(const uint2*)(zbuf + base + i * 128);
        __half2 h0 = *(__half2*)&u.x;
        __half2 h1 = *(__half2*)&u.y;
        float2 f0 = __half22float2(h0);
        float2 f1 = __half22float2(h1);
        z[i][0] = f0.x; z[i][1] = f0.y; z[i][2] = f1.x; z[i][3] = f1.y;
        mb[i] = *(const uchar4*)(maskb + base + i * 128);
        t4[i] = *(const int4*)(tids + lane * 4 + i * 128);
    }

    float a = -1e30f, b = -1e30f;
#pragma unroll
    for (int i = 0; i < 8; i++) {
        int ty[4] = {t4[i].x, t4[i].y, t4[i].z, t4[i].w};
#pragma unroll
        for (int s = 0; s < 4; s++) {
            if (ty[s] == 3) a = fmaxf(a, z[i][s]);
            if (ty[s] == 4) b = fmaxf(b, -z[i][s]);
        }
    }
#pragma unroll
    for (int o = 16; o; o >>= 1) {
        a = fmaxf(a, __shfl_xor_sync(0xffffffffu, a, o));
        b = fmaxf(b, __shfl_xor_sync(0xffffffffu, b, o));
    }
    float sa = 0.f, sb = 0.f;
#pragma unroll
    for (int i = 0; i < 8; i++) {
        int ty[4] = {t4[i].x, t4[i].y, t4[i].z, t4[i].w};
#pragma unroll
        for (int s = 0; s < 4; s++) {
            if (ty[s] == 3) sa += __expf(z[i][s] - a);
            if (ty[s] == 4) sb += __expf(-z[i][s] - b);
        }
    }
#pragma unroll
    for (int o = 16; o; o >>= 1) {
        sa += __shfl_xor_sync(0xffffffffu, sa, o);
        sb += __shfl_xor_sync(0xffffffffu, sb, o);
    }
    float inv3 = __frcp_rn(sa), inv4 = __frcp_rn(sb);

#pragma unroll
    for (int i = 0; i < 8; i++) {
        int ty[4] = {t4[i].x, t4[i].y, t4[i].z, t4[i].w};
        float mk[4] = {(float)mb[i].x, (float)mb[i].y,
                       (float)mb[i].z, (float)mb[i].w};
        float r0 = act_eval(z[i][0], ty[0], a, inv3, b, inv4) * mk[0] * 2.0f;
        float r1 = act_eval(z[i][1], ty[1], a, inv3, b, inv4) * mk[1] * 2.0f;
        float r2 = act_eval(z[i][2], ty[2], a, inv3, b, inv4) * mk[2] * 2.0f;
        float r3 = act_eval(z[i][3], ty[3], a, inv3, b, inv4) * mk[3] * 2.0f;
        __half2 h0 = __floats2half2_rn(r0, r1);
        __half2 h1 = __floats2half2_rn(r2, r3);
        uint2 u;
        u.x = *(uint32_t*)&h0;
        u.y = *(uint32_t*)&h1;
        *(uint2*)(hout + base + i * 128) = u;
    }
}

// ---------------------------------------------------------------------------
// act3 + head fused: activation, mask3*2 (byte mask), dot with W3 (10x1024),
// log_softmax.
// ---------------------------------------------------------------------------
__global__ __launch_bounds__(128)
void act3_head_kernel(const __half* __restrict__ zbuf, const int* __restrict__ tids,
                      const uint8_t* __restrict__ maskb,
                      const float* __restrict__ W3, const float* __restrict__ b3,
                      float* __restrict__ out) {
    const int lane = threadIdx.x & 31;
    const size_t row = (size_t)blockIdx.x * 4 + (threadIdx.x >> 5);
    const size_t base = row * HDIM + lane * 4;

    float z[8][4];
    uchar4 mb[8];
    int4 t4[8];
#pragma unroll
    for (int i = 0; i < 8; i++) {
        uint2 u = *(const uint2*)(zbuf + base + i * 128);
        __half2 h0 = *(__half2*)&u.x;
        __half2 h1 = *(__half2*)&u.y;
        float2 f0 = __half22float2(h0);
        float2 f1 = __half22float2(h1);
        z[i][0] = f0.x; z[i][1] = f0.y; z[i][2] = f1.x; z[i][3] = f1.y;
        mb[i] = *(const uchar4*)(maskb + base + i * 128);
        t4[i] = *(const int4*)(tids + lane * 4 + i * 128);
    }

    float a = -1e30f, b = -1e30f;
#pragma unroll
    for (int i = 0; i < 8; i++) {
        int ty[4] = {t4[i].x, t4[i].y, t4[i].z, t4[i].w};
#pragma unroll
        for (int s = 0; s < 4; s++) {
            if (ty[s] == 3) a = fmaxf(a, z[i][s]);
            if (ty[s] == 4) b = fmaxf(b, -z[i][s]);
        }
    }
#pragma unroll
    for (int o = 16; o; o >>= 1) {
        a = fmaxf(a, __shfl_xor_sync(0xffffffffu, a, o));
        b = fmaxf(b, __shfl_xor_sync(0xffffffffu, b, o));
    }
    float sa = 0.f, sb = 0.f;
#pragma unroll
    for (int i = 0; i < 8; i++) {
        int ty[4] = {t4[i].x, t4[i].y, t4[i].z, t4[i].w};
#pragma unroll
        for (int s = 0; s < 4; s++) {
            if (ty[s] == 3) sa += __expf(z[i][s] - a);
            if (ty[s] == 4) sb += __expf(-z[i][s] - b);
        }
    }
#pragma unroll
    for (int o = 16; o; o >>= 1) {
        sa += __shfl_xor_sync(0xffffffffu, sa, o);
        sb += __shfl_xor_sync(0xffffffffu, sb, o);
    }
    float inv3 = __frcp_rn(sa), inv4 = __frcp_rn(sb);

    float acc[10];
#pragma unroll
    for (int j = 0; j < 10; j++) acc[j] = 0.f;

#pragma unroll
    for (int i = 0; i < 8; i++) {
        int ty[4] = {t4[i].x, t4[i].y, t4[i].z, t4[i].w};
        float mk[4] = {(float)mb[i].x, (float)mb[i].y,
                       (float)mb[i].z, (float)mb[i].w};
        float r0 = act_eval(z[i][0], ty[0], a, inv3, b, inv4) * mk[0] * 2.0f;
        float r1 = act_eval(z[i][1], ty[1], a, inv3, b, inv4) * mk[1] * 2.0f;
        float r2 = act_eval(z[i][2], ty[2], a, inv3, b, inv4) * mk[2] * 2.0f;
        float r3 = act_eval(z[i][3], ty[3], a, inv3, b, inv4) * mk[3] * 2.0f;
        int colbase = lane * 4 + i * 128;
#pragma unroll
        for (int j = 0; j < 10; j++) {
            float4 w = *(const float4*)(W3 + (size_t)j * HDIM + colbase);
            acc[j] += r0 * w.x + r1 * w.y + r2 * w.z + r3 * w.w;
        }
    }
#pragma unroll
    for (int j = 0; j < 10; j++)
#pragma unroll
        for (int o = 16; o; o >>= 1)
            acc[j] += __shfl_xor_sync(0xffffffffu, acc[j], o);

    float logits[10];
    float m = -1e30f;
#pragma unroll
    for (int j = 0; j < 10; j++) {
        logits[j] = acc[j] + __ldg(b3 + j);
        m = fmaxf(m, logits[j]);
    }
    float s = 0.f;
#pragma unroll
    for (int j = 0; j < 10; j++) s += __expf(logits[j] - m);
    float lse = m + logf(s);
    if (lane == 0) {
#pragma unroll
        for (int j = 0; j < 10; j++) out[row * 10 + j] = logits[j] - lse;
    }
}

// ---------------------------------------------------------------------------
// Launch
// ---------------------------------------------------------------------------
extern "C" void kernel_launch(void* const* d_in, const int* in_sizes, int n_in,
                              void* d_out, int out_size) {
    const float* x     = (const float*)d_in[0];
    const float* W0    = (const float*)d_in[1];
    const float* b0    = (const float*)d_in[2];
    const float* W1    = (const float*)d_in[3];
    const float* b1    = (const float*)d_in[4];
    const float* W2    = (const float*)d_in[5];
    const float* b2    = (const float*)d_in[6];
    const float* W3    = (const float*)d_in[7];
    const float* b3    = (const float*)d_in[8];
    const float* mask1 = (const float*)d_in[9];
    const float* mask2 = (const float*)d_in[10];
    const float* mask3 = (const float*)d_in[11];
    const int* type_ids = (const int*)d_in[12];

    __half* zbuf = nullptr;
    __half* hbuf = nullptr;
    __half* xh   = nullptr;
    __half* w0h  = nullptr;
    __half* w1h  = nullptr;
    __half* w2h  = nullptr;
    uint8_t* mb  = nullptr;
    cudaGetSymbolAddress((void**)&zbuf, g_z);
    cudaGetSymbolAddress((void**)&hbuf, g_h);
    cudaGetSymbolAddress((void**)&xh, g_xh);
    cudaGetSymbolAddress((void**)&w0h, g_w0h);
    cudaGetSymbolAddress((void**)&w1h, g_w1h);
    cudaGetSymbolAddress((void**)&w2h, g_w2h);
    cudaGetSymbolAddress((void**)&mb, g_mb);
    float* out = (float*)d_out;

    const int smemBytes = GSTAGES * STG_BYTES + 1024;
    cudaFuncSetAttribute(gemm_fp16_kernel,
                         cudaFuncAttributeMaxDynamicSharedMemorySize, smemBytes);

    // fp32 -> fp16 conversions
    f2h_kernel<<<1024, 256>>>(x, xh, (int)((size_t)BATCH * DIN / 4));
    f2h_kernel<<<256, 256>>>(W0, w0h, HDIM * DIN / 4);
    f2h_kernel<<<256, 256>>>(W1, w1h, HDIM * HDIM / 4);
    f2h_kernel<<<256, 256>>>(W2, w2h, HDIM * HDIM / 4);

    const size_t maskElems = (size_t)BATCH * HDIM;
    float* mdst = out + (size_t)BATCH * 10;

    const int ngrid = NGEMMB + COPYB;
    gemm_fp16_kernel<<<ngrid, 256, smemBytes>>>(xh, w0h, b0, zbuf, DIN,
                                                mask1, mdst, mb);
    act_kernel<<<BATCH / 4, 128>>>(zbuf, type_ids, mb, hbuf);
    gemm_fp16_kernel<<<ngrid, 256, smemBytes>>>(hbuf, w1h, b1, zbuf, HDIM,
                                                mask2, mdst + maskElems, mb);
    act_kernel<<<BATCH / 4, 128>>>(zbuf, type_ids + HDIM, mb, hbuf);
    gemm_fp16_kernel<<<ngrid, 256, smemBytes>>>(hbuf, w2h, b2, zbuf, HDIM,
                                                mask3, mdst + 2 * maskElems, mb);
    act3_head_kernel<<<BATCH / 4, 128>>>(zbuf, type_ids + 2 * HDIM, mb,
                                         W3, b3, out);
}

// round 14
// speedup vs baseline: 1.6452x; 1.5729x over previous
#include <cuda_runtime.h>
#include <cuda_fp16.h>
#include <cstdint>
#include <cstddef>

#define BATCH 32768
#define HDIM  1024
#define DIN   784

// Scratch buffers (device globals: no allocation allowed)
static __device__ __half g_z[(size_t)BATCH * HDIM];              // GEMM fp16 out
static __device__ __half g_h[(size_t)BATCH * HDIM];              // act fp16 out
static __device__ __half g_xh[(size_t)BATCH * DIN];              // x fp16
static __device__ __half g_w0h[(size_t)HDIM * DIN];
static __device__ __half g_w1h[(size_t)HDIM * HDIM];
static __device__ __half g_w2h[(size_t)HDIM * HDIM];

// ---------------------------------------------------------------------------
// helpers
// ---------------------------------------------------------------------------
__device__ __forceinline__ uint32_t smem_u32(const void* p) {
    return (uint32_t)__cvta_generic_to_shared(p);
}
#define SWZ128(o) ((o) ^ (((o) >> 3) & 0x70))

__device__ __forceinline__ void cp16(uint32_t dst, const void* src, int bytes) {
    asm volatile("cp.async.cg.shared.global [%0], [%1], 16, %2;\n"
                 :: "r"(dst), "l"(src), "r"(bytes));
}
__device__ __forceinline__ void cp_commit() {
    asm volatile("cp.async.commit_group;\n");
}

__device__ __forceinline__ void ldm_x4(uint32_t (&r)[4], uint32_t addr) {
    asm volatile("ldmatrix.sync.aligned.m8n8.x4.shared.b16 {%0,%1,%2,%3}, [%4];"
                 : "=r"(r[0]), "=r"(r[1]), "=r"(r[2]), "=r"(r[3]) : "r"(addr));
}

__device__ __forceinline__ void mma_fp16(float d[4], const uint32_t a[4],
                                         const uint32_t b0, const uint32_t b1) {
    asm volatile(
        "mma.sync.aligned.m16n8k16.row.col.f32.f16.f16.f32 "
        "{%0,%1,%2,%3}, {%4,%5,%6,%7}, {%8,%9}, {%0,%1,%2,%3};\n"
        : "+f"(d[0]), "+f"(d[1]), "+f"(d[2]), "+f"(d[3])
        : "r"(a[0]), "r"(a[1]), "r"(a[2]), "r"(a[3]), "r"(b0), "r"(b1));
}

// ---------------------------------------------------------------------------
// fp32 -> fp16 convert (grid-stride, float4 granularity)
// ---------------------------------------------------------------------------
__global__ __launch_bounds__(256)
void f2h_kernel(const float* __restrict__ src, __half* __restrict__ dst, int n4) {
    for (int i = blockIdx.x * 256 + threadIdx.x; i < n4; i += gridDim.x * 256) {
        float4 v = *(const float4*)(src + (size_t)i * 4);
        __half2 h0 = __floats2half2_rn(v.x, v.y);
        __half2 h1 = __floats2half2_rn(v.z, v.w);
        uint2 u;
        u.x = *(uint32_t*)&h0;
        u.y = *(uint32_t*)&h1;
        *(uint2*)(dst + (size_t)i * 4) = u;
    }
}

// ---------------------------------------------------------------------------
// GEMM: C[M, HDIM](fp16) = A[M,K](f16) @ W[HDIM,K](f16)^T + bias
// CTA 128x128, BK=64 halves, 3-stage cp.async, SW128, ldmatrix, m16n8k16,
// f32 accum. 8 warps, warp tile 64x32. Single barrier per k-iter + kk-level
// fragment double buffering.  (R8 config — best measured; untouched.)
// ---------------------------------------------------------------------------
#define GSTAGES 3
#define AB_BYTES 16384            // 128 rows * 128B
#define STG_BYTES (2 * AB_BYTES)

__device__ __forceinline__ void load_chunk(const __half* __restrict__ A,
                                           const __half* __restrict__ W,
                                           int K, size_t blockRow, int blockCol,
                                           int k0, uint32_t stage_base, int tid) {
#pragma unroll
    for (int i = 0; i < 4; i++) {
        int u = tid + i * 256;          // 0..1023
        int row = u >> 3;               // 0..127
        int c16 = u & 7;
        int col = k0 + c16 * 8;
        int vb = (col + 8 <= K) ? 16 : 0;
        const __half* src = A + (blockRow + (size_t)row) * (size_t)K +
                            (vb ? col : k0);
        uint32_t off = (uint32_t)(row * 128 + c16 * 16);
        cp16(stage_base + SWZ128(off), src, vb);
    }
#pragma unroll
    for (int i = 0; i < 4; i++) {
        int u = tid + i * 256;
        int row = u >> 3;
        int c16 = u & 7;
        int col = k0 + c16 * 8;
        int vb = (col + 8 <= K) ? 16 : 0;
        const __half* src = W + (size_t)(blockCol + row) * (size_t)K +
                            (vb ? col : k0);
        uint32_t off = (uint32_t)(row * 128 + c16 * 16);
        cp16(stage_base + AB_BYTES + SWZ128(off), src, vb);
    }
}

__global__ __launch_bounds__(256)
void gemm_fp16_kernel(const __half* __restrict__ A, const __half* __restrict__ W,
                      const float* __restrict__ bias, __half* __restrict__ C,
                      int K) {
    extern __shared__ char dsm[];
    const uint32_t sbase = (smem_u32(dsm) + 1023u) & ~1023u;

    const int tid  = threadIdx.x;
    const int lane = tid & 31;
    const int warp = tid >> 5;
    const int wm   = (warp & 1) * 64;
    const int wn   = (warp >> 1) * 32;

    const size_t blockRow = (size_t)blockIdx.y * 128;
    const int    blockCol = blockIdx.x * 128;

    float acc[4][4][4];
#pragma unroll
    for (int mt = 0; mt < 4; mt++)
#pragma unroll
        for (int nt = 0; nt < 4; nt++)
#pragma unroll
            for (int r = 0; r < 4; r++) acc[mt][nt][r] = 0.f;

    const int nK = (K + 63) / 64;

    // ldmatrix lane-addressing precompute
    const int lrow = lane & 7;
    const int lmat = lane >> 3;
    const int a_radd = (lmat & 1) * 8;
    const int a_kadd = (lmat >> 1) * 16;
    const int b_nadd = (lmat >> 1) * 8;
    const int b_kadd = (lmat & 1) * 16;

    // Prologue: stages 0, 1
#pragma unroll
    for (int s = 0; s < GSTAGES - 1; s++) {
        load_chunk(A, W, K, blockRow, blockCol, s * 64,
                   sbase + (uint32_t)s * STG_BYTES, tid);
        cp_commit();
    }
    asm volatile("cp.async.wait_group 1;\n");
    __syncthreads();

    uint32_t af[2][4][4];
    uint32_t bf[2][2][4];

#define LOAD_FRAGS(buf, stageA, stageB, kbyte)                                \
    do {                                                                      \
        _Pragma("unroll")                                                     \
        for (int mt = 0; mt < 4; mt++) {                                      \
            int row = wm + mt * 16 + a_radd + lrow;                           \
            uint32_t off = (uint32_t)(row * 128 + (kbyte) + a_kadd);          \
            ldm_x4(af[buf][mt], (stageA) + SWZ128(off));                      \
        }                                                                     \
        _Pragma("unroll")                                                     \
        for (int np = 0; np < 2; np++) {                                      \
            int row = wn + np * 16 + b_nadd + lrow;                           \
            uint32_t off = (uint32_t)(row * 128 + (kbyte) + b_kadd);          \
            ldm_x4(bf[buf][np], (stageB) + SWZ128(off));                      \
        }                                                                     \
    } while (0)

    {
        uint32_t aB0 = sbase;
        uint32_t bB0 = sbase + AB_BYTES;
        LOAD_FRAGS(0, aB0, bB0, 0);
    }

    for (int kt = 0; kt < nK; ++kt) {
        const uint32_t aB = sbase + (uint32_t)(kt % GSTAGES) * STG_BYTES;
        const uint32_t bB = aB + AB_BYTES;

#pragma unroll
        for (int kk = 0; kk < 4; kk++) {
            const int cur = kk & 1;
            if (kk < 3) LOAD_FRAGS(cur ^ 1, aB, bB, (kk + 1) * 32);
#pragma unroll
            for (int mt = 0; mt < 4; mt++) {
#pragma unroll
                for (int nt = 0; nt < 4; nt++) {
                    mma_fp16(acc[mt][nt], af[cur][mt],
                             bf[cur][nt >> 1][(nt & 1) * 2],
                             bf[cur][nt >> 1][(nt & 1) * 2 + 1]);
                }
            }
        }

        int pf = kt + GSTAGES - 1;
        if (pf < nK)
            load_chunk(A, W, K, blockRow, blockCol, pf * 64,
                       sbase + (uint32_t)(pf % GSTAGES) * STG_BYTES, tid);
        cp_commit();
        asm volatile("cp.async.wait_group 1;\n");
        __syncthreads();

        if (kt + 1 < nK) {
            uint32_t aN = sbase + (uint32_t)((kt + 1) % GSTAGES) * STG_BYTES;
            uint32_t bN = aN + AB_BYTES;
            LOAD_FRAGS(0, aN, bN, 0);
        }
    }

    // Epilogue: bias + fp16 store
    const int g  = lane >> 2;
    const int tq = lane & 3;
#pragma unroll
    for (int mt = 0; mt < 4; mt++) {
        size_t row = blockRow + (size_t)(wm + mt * 16 + g);
#pragma unroll
        for (int nt = 0; nt < 4; nt++) {
            int c0 = blockCol + wn + nt * 8 + tq * 2;
            float bv0 = __ldg(bias + c0), bv1 = __ldg(bias + c0 + 1);
            __half2 v0 = __floats2half2_rn(acc[mt][nt][0] + bv0,
                                           acc[mt][nt][1] + bv1);
            __half2 v1 = __floats2half2_rn(acc[mt][nt][2] + bv0,
                                           acc[mt][nt][3] + bv1);
            *(__half2*)(C + row * HDIM + c0)       = v0;
            *(__half2*)(C + (row + 8) * HDIM + c0) = v1;
        }
    }
}

// ---------------------------------------------------------------------------
// activation helpers — BRANCHLESS: compute all candidates, select.
// Types are random per column, so every warp contains nearly all 7 types;
// the divergent if/else chain executed the union of all bodies anyway plus
// ~7 BSSY/BSYNC pairs per group. Straight-line + SEL removes the branches.
// ---------------------------------------------------------------------------
__device__ __forceinline__ float tanh_ap(float x) {
    float r;
    asm("tanh.approx.f32 %0, %1;" : "=f"(r) : "f"(x));
    return r;
}

__device__ __forceinline__ float act_eval(float x, int c, float M3, float inv3,
                                          float M4, float inv4) {
    float re = fmaxf(x, 0.0f);
    float t  = tanh_ap(x);
    float sg = 0.5f * tanh_ap(0.5f * x) + 0.5f;
    float e3 = __expf(x - M3) * inv3;
    float e4 = __expf(-x - M4) * inv4;
    float g  = 0.5f * x * (1.0f + erff(x * 0.70710678118654752f));
    float lr = fmaxf(x, 0.01f * x);   // == x>=0 ? x : 0.01x (exact)
    float r = re;
    r = (c == 1) ? t  : r;
    r = (c == 2) ? sg : r;
    r = (c == 3) ? e3 : r;
    r = (c == 4) ? e4 : r;
    r = (c == 5) ? g  : r;
    r = (c == 6) ? lr : r;
    return r;
}

// ---------------------------------------------------------------------------
// Warp-per-row activation: reads fp16 GEMM out, f32 mask; writes fp16
// (act*mask*2) + f32 mask passthrough to output region.
// ---------------------------------------------------------------------------
__global__ __launch_bounds__(128)
void act_kernel(const __half* __restrict__ zbuf, const int* __restrict__ tids,
                const float* __restrict__ mask, float* __restrict__ mask_out,
                __half* __restrict__ hout) {
    const int lane = threadIdx.x & 31;
    const size_t row = (size_t)blockIdx.x * 4 + (threadIdx.x >> 5);
    const size_t base = row * HDIM + lane * 4;

    float z[8][4];
    float4 m4[8];
    int4 t4[8];
#pragma unroll
    for (int i = 0; i < 8; i++) {
        uint2 u = *(const uint2*)(zbuf + base + i * 128);
        __half2 h0 = *(__half2*)&u.x;
        __half2 h1 = *(__half2*)&u.y;
        float2 f0 = __half22float2(h0);
        float2 f1 = __half22float2(h1);
        z[i][0] = f0.x; z[i][1] = f0.y; z[i][2] = f1.x; z[i][3] = f1.y;
        m4[i] = *(const float4*)(mask + base + i * 128);
        t4[i] = *(const int4*)(tids + lane * 4 + i * 128);
        *(float4*)(mask_out + base + i * 128) = m4[i];
    }

    float a = -1e30f, b = -1e30f;
#pragma unroll
    for (int i = 0; i < 8; i++) {
        int ty[4] = {t4[i].x, t4[i].y, t4[i].z, t4[i].w};
#pragma unroll
        for (int s = 0; s < 4; s++) {
            a = fmaxf(a, (ty[s] == 3) ? z[i][s]  : -1e30f);
            b = fmaxf(b, (ty[s] == 4) ? -z[i][s] : -1e30f);
        }
    }
#pragma unroll
    for (int o = 16; o; o >>= 1) {
        a = fmaxf(a, __shfl_xor_sync(0xffffffffu, a, o));
        b = fmaxf(b, __shfl_xor_sync(0xffffffffu, b, o));
    }
    float sa = 0.f, sb = 0.f;
#pragma unroll
    for (int i = 0; i < 8; i++) {
        int ty[4] = {t4[i].x, t4[i].y, t4[i].z, t4[i].w};
#pragma unroll
        for (int s = 0; s < 4; s++) {
            float ea = __expf(z[i][s] - a);
            float eb = __expf(-z[i][s] - b);
            sa += (ty[s] == 3) ? ea : 0.0f;
            sb += (ty[s] == 4) ? eb : 0.0f;
        }
    }
#pragma unroll
    for (int o = 16; o; o >>= 1) {
        sa += __shfl_xor_sync(0xffffffffu, sa, o);
        sb += __shfl_xor_sync(0xffffffffu, sb, o);
    }
    float inv3 = __frcp_rn(sa), inv4 = __frcp_rn(sb);

#pragma unroll
    for (int i = 0; i < 8; i++) {
        int ty[4] = {t4[i].x, t4[i].y, t4[i].z, t4[i].w};
        float mk[4] = {m4[i].x, m4[i].y, m4[i].z, m4[i].w};
        float r0 = act_eval(z[i][0], ty[0], a, inv3, b, inv4) * mk[0] * 2.0f;
        float r1 = act_eval(z[i][1], ty[1], a, inv3, b, inv4) * mk[1] * 2.0f;
        float r2 = act_eval(z[i][2], ty[2], a, inv3, b, inv4) * mk[2] * 2.0f;
        float r3 = act_eval(z[i][3], ty[3], a, inv3, b, inv4) * mk[3] * 2.0f;
        __half2 h0 = __floats2half2_rn(r0, r1);
        __half2 h1 = __floats2half2_rn(r2, r3);
        uint2 u;
        u.x = *(uint32_t*)&h0;
        u.y = *(uint32_t*)&h1;
        *(uint2*)(hout + base + i * 128) = u;
    }
}

// ---------------------------------------------------------------------------
// act3 + head fused: activation, mask3*2, dot with W3 (10x1024), log_softmax.
// ---------------------------------------------------------------------------
__global__ __launch_bounds__(128)
void act3_head_kernel(const __half* __restrict__ zbuf, const int* __restrict__ tids,
                      const float* __restrict__ mask, float* __restrict__ mask_out,
                      const float* __restrict__ W3, const float* __restrict__ b3,
                      float* __restrict__ out) {
    const int lane = threadIdx.x & 31;
    const size_t row = (size_t)blockIdx.x * 4 + (threadIdx.x >> 5);
    const size_t base = row * HDIM + lane * 4;

    float z[8][4];
    float4 m4[8];
    int4 t4[8];
#pragma unroll
    for (int i = 0; i < 8; i++) {
        uint2 u = *(const uint2*)(zbuf + base + i * 128);
        __half2 h0 = *(__half2*)&u.x;
        __half2 h1 = *(__half2*)&u.y;
        float2 f0 = __half22float2(h0);
        float2 f1 = __half22float2(h1);
        z[i][0] = f0.x; z[i][1] = f0.y; z[i][2] = f1.x; z[i][3] = f1.y;
        m4[i] = *(const float4*)(mask + base + i * 128);
        t4[i] = *(const int4*)(tids + lane * 4 + i * 128);
        *(float4*)(mask_out + base + i * 128) = m4[i];
    }

    float a = -1e30f, b = -1e30f;
#pragma unroll
    for (int i = 0; i < 8; i++) {
        int ty[4] = {t4[i].x, t4[i].y, t4[i].z, t4[i].w};
#pragma unroll
        for (int s = 0; s < 4; s++) {
            a = fmaxf(a, (ty[s] == 3) ? z[i][s]  : -1e30f);
            b = fmaxf(b, (ty[s] == 4) ? -z[i][s] : -1e30f);
        }
    }
#pragma unroll
    for (int o = 16; o; o >>= 1) {
        a = fmaxf(a, __shfl_xor_sync(0xffffffffu, a, o));
        b = fmaxf(b, __shfl_xor_sync(0xffffffffu, b, o));
    }
    float sa = 0.f, sb = 0.f;
#pragma unroll
    for (int i = 0; i < 8; i++) {
        int ty[4] = {t4[i].x, t4[i].y, t4[i].z, t4[i].w};
#pragma unroll
        for (int s = 0; s < 4; s++) {
            float ea = __expf(z[i][s] - a);
            float eb = __expf(-z[i][s] - b);
            sa += (ty[s] == 3) ? ea : 0.0f;
            sb += (ty[s] == 4) ? eb : 0.0f;
        }
    }
#pragma unroll
    for (int o = 16; o; o >>= 1) {
        sa += __shfl_xor_sync(0xffffffffu, sa, o);
        sb += __shfl_xor_sync(0xffffffffu, sb, o);
    }
    float inv3 = __frcp_rn(sa), inv4 = __frcp_rn(sb);

    float acc[10];
#pragma unroll
    for (int j = 0; j < 10; j++) acc[j] = 0.f;

#pragma unroll
    for (int i = 0; i < 8; i++) {
        int ty[4] = {t4[i].x, t4[i].y, t4[i].z, t4[i].w};
        float mk[4] = {m4[i].x, m4[i].y, m4[i].z, m4[i].w};
        float r0 = act_eval(z[i][0], ty[0], a, inv3, b, inv4) * mk[0] * 2.0f;
        float r1 = act_eval(z[i][1], ty[1], a, inv3, b, inv4) * mk[1] * 2.0f;
        float r2 = act_eval(z[i][2], ty[2], a, inv3, b, inv4) * mk[2] * 2.0f;
        float r3 = act_eval(z[i][3], ty[3], a, inv3, b, inv4) * mk[3] * 2.0f;
        int colbase = lane * 4 + i * 128;
#pragma unroll
        for (int j = 0; j < 10; j++) {
            float4 w = *(const float4*)(W3 + (size_t)j * HDIM + colbase);
            acc[j] += r0 * w.x + r1 * w.y + r2 * w.z + r3 * w.w;
        }
    }
#pragma unroll
    for (int j = 0; j < 10; j++)
#pragma unroll
        for (int o = 16; o; o >>= 1)
            acc[j] += __shfl_xor_sync(0xffffffffu, acc[j], o);

    float logits[10];
    float m = -1e30f;
#pragma unroll
    for (int j = 0; j < 10; j++) {
        logits[j] = acc[j] + __ldg(b3 + j);
        m = fmaxf(m, logits[j]);
    }
    float s = 0.f;
#pragma unroll
    for (int j = 0; j < 10; j++) s += __expf(logits[j] - m);
    float lse = m + logf(s);
    if (lane == 0) {
#pragma unroll
        for (int j = 0; j < 10; j++) out[row * 10 + j] = logits[j] - lse;
    }
}

// ---------------------------------------------------------------------------
// Launch
// ---------------------------------------------------------------------------
extern "C" void kernel_launch(void* const* d_in, const int* in_sizes, int n_in,
                              void* d_out, int out_size) {
    const float* x     = (const float*)d_in[0];
    const float* W0    = (const float*)d_in[1];
    const float* b0    = (const float*)d_in[2];
    const float* W1    = (const float*)d_in[3];
    const float* b1    = (const float*)d_in[4];
    const float* W2    = (const float*)d_in[5];
    const float* b2    = (const float*)d_in[6];
    const float* W3    = (const float*)d_in[7];
    const float* b3    = (const float*)d_in[8];
    const float* mask1 = (const float*)d_in[9];
    const float* mask2 = (const float*)d_in[10];
    const float* mask3 = (const float*)d_in[11];
    const int* type_ids = (const int*)d_in[12];

    __half* zbuf = nullptr;
    __half* hbuf = nullptr;
    __half* xh   = nullptr;
    __half* w0h  = nullptr;
    __half* w1h  = nullptr;
    __half* w2h  = nullptr;
    cudaGetSymbolAddress((void**)&zbuf, g_z);
    cudaGetSymbolAddress((void**)&hbuf, g_h);
    cudaGetSymbolAddress((void**)&xh, g_xh);
    cudaGetSymbolAddress((void**)&w0h, g_w0h);
    cudaGetSymbolAddress((void**)&w1h, g_w1h);
    cudaGetSymbolAddress((void**)&w2h, g_w2h);
    float* out = (float*)d_out;

    const int smemBytes = GSTAGES * STG_BYTES + 1024;
    cudaFuncSetAttribute(gemm_fp16_kernel,
                         cudaFuncAttributeMaxDynamicSharedMemorySize, smemBytes);

    // fp32 -> fp16 conversions
    f2h_kernel<<<1024, 256>>>(x, xh, (int)((size_t)BATCH * DIN / 4));
    f2h_kernel<<<256, 256>>>(W0, w0h, HDIM * DIN / 4);
    f2h_kernel<<<256, 256>>>(W1, w1h, HDIM * HDIM / 4);
    f2h_kernel<<<256, 256>>>(W2, w2h, HDIM * HDIM / 4);

    const size_t maskElems = (size_t)BATCH * HDIM;
    float* mdst = out + (size_t)BATCH * 10;

    dim3 gg(HDIM / 128, BATCH / 128);
    gemm_fp16_kernel<<<gg, 256, smemBytes>>>(xh, w0h, b0, zbuf, DIN);
    act_kernel<<<BATCH / 4, 128>>>(zbuf, type_ids, mask1, mdst, hbuf);
    gemm_fp16_kernel<<<gg, 256, smemBytes>>>(hbuf, w1h, b1, zbuf, HDIM);
    act_kernel<<<BATCH / 4, 128>>>(zbuf, type_ids + HDIM, mask2, mdst + maskElems,
                                   hbuf);
    gemm_fp16_kernel<<<gg, 256, smemBytes>>>(hbuf, w2h, b2, zbuf, HDIM);
    act3_head_kernel<<<BATCH / 4, 128>>>(zbuf, type_ids + 2 * HDIM, mask3,
                                         mdst + 2 * maskElems, W3, b3, out);
}